// round 3
// baseline (speedup 1.0000x reference)
#include <cuda_runtime.h>

#define N_NODES 100000
#define F_IN    256
#define F_HID   64
#define F_OUT   40

// Scratch (static device globals — no allocation allowed)
__device__ float g_dis[N_NODES];              // deg accumulator, then rsqrt(deg+1)
__device__ float g_h1[N_NODES * F_HID];       // x @ W1
__device__ float g_agg1[N_NODES * F_HID];     // aggregated layer-1, then relu(agg+b1)
__device__ float g_h2[N_NODES * F_OUT];       // relu_out @ W2

// ---------------------------------------------------------------------------
// Degree / normalization
// ---------------------------------------------------------------------------
__global__ void k_zero_deg(int n) {
    int i = blockIdx.x * blockDim.x + threadIdx.x;
    if (i < n) g_dis[i] = 0.0f;
}

__global__ void k_deg(const int* __restrict__ ei,
                      const float* __restrict__ ew, int E) {
    int e = blockIdx.x * blockDim.x + threadIdx.x;
    if (e < E) {
        int c = ei[E + e];                 // col = second row of edge_index
        atomicAdd(&g_dis[c], ew[e]);
    }
}

__global__ void k_dis(int n) {
    int i = blockIdx.x * blockDim.x + threadIdx.x;
    if (i < n) g_dis[i] = rsqrtf(g_dis[i] + 1.0f);   // +1 = self-loop weight
}

// ---------------------------------------------------------------------------
// GEMM1: g_h1[N,64] = x[N,256] @ W1[256,64]
// Block: 256 threads, 32 rows. K chunked by 64. smem float4 for W.
// ---------------------------------------------------------------------------
__global__ void k_gemm1(const float* __restrict__ x,
                        const float* __restrict__ W1) {
    __shared__ float  xs[32][68];          // pad 68 to dodge bank conflicts
    __shared__ float4 ws4[64 * 16];        // 64 k-rows x 64 cols (16 float4/row)

    int t    = threadIdx.x;
    int row0 = blockIdx.x * 32;
    int row  = t >> 3;                     // 0..31
    int colg = t & 7;                      // 0..7 -> cols colg*8 .. +7

    float acc0 = 0.f, acc1 = 0.f, acc2 = 0.f, acc3 = 0.f;
    float acc4 = 0.f, acc5 = 0.f, acc6 = 0.f, acc7 = 0.f;

    for (int kc = 0; kc < 4; kc++) {
        // load W chunk: 64x64 floats = 1024 float4
        const float4* w4 = (const float4*)(W1 + kc * 64 * 64);
        #pragma unroll
        for (int j = 0; j < 4; j++)
            ws4[t + j * 256] = w4[t + j * 256];
        // load x tile: 32 rows x 64 k = 512 float4
        #pragma unroll
        for (int j = 0; j < 2; j++) {
            int idx4 = t + j * 256;
            int r  = idx4 >> 4;
            int k4 = idx4 & 15;
            float4 v = *(const float4*)(x + (long long)(row0 + r) * F_IN + kc * 64 + k4 * 4);
            *(float4*)(&xs[r][k4 * 4]) = v;
        }
        __syncthreads();

        #pragma unroll
        for (int kk = 0; kk < 64; kk++) {
            float  xv = xs[row][kk];
            float4 w0 = ws4[kk * 16 + colg * 2];
            float4 w1 = ws4[kk * 16 + colg * 2 + 1];
            acc0 += xv * w0.x; acc1 += xv * w0.y;
            acc2 += xv * w0.z; acc3 += xv * w0.w;
            acc4 += xv * w1.x; acc5 += xv * w1.y;
            acc6 += xv * w1.z; acc7 += xv * w1.w;
        }
        __syncthreads();
    }

    float* o = g_h1 + (long long)(row0 + row) * F_HID + colg * 8;
    *(float4*)(o)     = make_float4(acc0, acc1, acc2, acc3);
    *(float4*)(o + 4) = make_float4(acc4, acc5, acc6, acc7);
}

// ---------------------------------------------------------------------------
// Layer-1 edge aggregation: one warp per edge, 64 features
// ---------------------------------------------------------------------------
__global__ void k_zero_agg1(int n) {
    int i = blockIdx.x * blockDim.x + threadIdx.x;
    if (i < n) g_agg1[i] = 0.0f;
}

__global__ void k_agg1(const int* __restrict__ ei,
                       const float* __restrict__ ew, int E) {
    int gtid = blockIdx.x * blockDim.x + threadIdx.x;
    int warp = gtid >> 5;
    int lane = threadIdx.x & 31;
    if (warp >= E) return;
    int r = ei[warp];
    int c = ei[E + warp];
    float nrm = g_dis[r] * ew[warp] * g_dis[c];
    const float* hr = g_h1 + (long long)r * F_HID;
    float v0 = hr[lane];
    float v1 = hr[lane + 32];
    float* oc = g_agg1 + (long long)c * F_HID;
    atomicAdd(&oc[lane],      nrm * v0);
    atomicAdd(&oc[lane + 32], nrm * v1);
}

// self loop + bias + relu, in place into g_agg1
__global__ void k_selfrelu(const float* __restrict__ b1, int n) {
    int idx = blockIdx.x * blockDim.x + threadIdx.x;
    if (idx >= n) return;
    int i = idx >> 6;
    int f = idx & 63;
    float d = g_dis[i];
    float v = g_agg1[idx] + d * d * g_h1[idx] + b1[f];
    g_agg1[idx] = fmaxf(v, 0.0f);
}

// ---------------------------------------------------------------------------
// GEMM2: g_h2[N,40] = relu_out[N,64] @ W2[64,40]
// ---------------------------------------------------------------------------
__global__ void k_gemm2(const float* __restrict__ W2) {
    __shared__ float rs[32][68];
    __shared__ float ws2[64 * 40];

    int t    = threadIdx.x;
    int row0 = blockIdx.x * 32;
    int row  = t >> 3;
    int colg = t & 7;                       // cols colg*5 .. +4

    // load W2 (2560 floats)
    #pragma unroll
    for (int j = 0; j < 10; j++)
        ws2[t + j * 256] = W2[t + j * 256];
    // load relu tile (32x64 = 512 float4)
    #pragma unroll
    for (int j = 0; j < 2; j++) {
        int idx4 = t + j * 256;
        int r  = idx4 >> 4;
        int k4 = idx4 & 15;
        float4 v = *(const float4*)(g_agg1 + (long long)(row0 + r) * F_HID + k4 * 4);
        *(float4*)(&rs[r][k4 * 4]) = v;
    }
    __syncthreads();

    float acc[5] = {0.f, 0.f, 0.f, 0.f, 0.f};
    #pragma unroll
    for (int kk = 0; kk < 64; kk++) {
        float a = rs[row][kk];
        #pragma unroll
        for (int j = 0; j < 5; j++)
            acc[j] += a * ws2[kk * 40 + colg * 5 + j];
    }

    float* o = g_h2 + (long long)(row0 + row) * F_OUT + colg * 5;
    #pragma unroll
    for (int j = 0; j < 5; j++) o[j] = acc[j];
}

// init output with bias + self-loop contribution
__global__ void k_init_out(const float* __restrict__ b2,
                           float* __restrict__ out, int n) {
    int idx = blockIdx.x * blockDim.x + threadIdx.x;
    if (idx >= n) return;
    int i = idx / F_OUT;
    int f = idx - i * F_OUT;
    float d = g_dis[i];
    out[idx] = b2[f] + d * d * g_h2[idx];
}

// Layer-2 edge aggregation: one warp per edge, 40 features
__global__ void k_agg2(const int* __restrict__ ei,
                       const float* __restrict__ ew,
                       float* __restrict__ out, int E) {
    int gtid = blockIdx.x * blockDim.x + threadIdx.x;
    int warp = gtid >> 5;
    int lane = threadIdx.x & 31;
    if (warp >= E) return;
    int r = ei[warp];
    int c = ei[E + warp];
    float nrm = g_dis[r] * ew[warp] * g_dis[c];
    const float* hr = g_h2 + (long long)r * F_OUT;
    float* oc = out + (long long)c * F_OUT;
    atomicAdd(&oc[lane], nrm * hr[lane]);
    if (lane < 8)
        atomicAdd(&oc[lane + 32], nrm * hr[lane + 32]);
}

// ---------------------------------------------------------------------------
extern "C" void kernel_launch(void* const* d_in, const int* in_sizes, int n_in,
                              void* d_out, int out_size) {
    const float* x  = (const float*)d_in[0];
    const int*   ei = (const int*)d_in[1];
    const float* ew = (const float*)d_in[2];
    const float* W1 = (const float*)d_in[3];
    const float* b1 = (const float*)d_in[4];
    const float* W2 = (const float*)d_in[5];
    const float* b2 = (const float*)d_in[6];
    float* out = (float*)d_out;

    int N = in_sizes[0] / F_IN;     // 100000
    int E = in_sizes[2];            // 1600000

    k_zero_deg<<<(N + 255) / 256, 256>>>(N);
    k_deg<<<(E + 255) / 256, 256>>>(ei, ew, E);
    k_dis<<<(N + 255) / 256, 256>>>(N);

    k_gemm1<<<N / 32, 256>>>(x, W1);

    int n1 = N * F_HID;
    k_zero_agg1<<<(n1 + 255) / 256, 256>>>(n1);
    k_agg1<<<(E + 7) / 8, 256>>>(ei, ew, E);
    k_selfrelu<<<(n1 + 255) / 256, 256>>>(b1, n1);

    k_gemm2<<<N / 32, 256>>>(W2);

    int n2 = N * F_OUT;
    k_init_out<<<(n2 + 255) / 256, 256>>>(b2, out, n2);
    k_agg2<<<(E + 7) / 8, 256>>>(ei, ew, out, E);
}

// round 4
// speedup vs baseline: 2.5572x; 2.5572x over previous
#include <cuda_runtime.h>

#define N_NODES 100000
#define F_IN    256
#define F_HID   64
#define F_OUT   40

// Scratch (static device globals — no allocation allowed)
__device__ float g_dis[N_NODES];              // deg accumulator, then rsqrt(deg+1)
__device__ float g_h1[N_NODES * F_HID];       // x @ W1
__device__ float g_agg1[N_NODES * F_HID];     // aggregated layer-1, then relu(agg+b1)
__device__ float g_h2[N_NODES * F_OUT];       // relu_out @ W2

// ---------------------------------------------------------------------------
// Degree / normalization
// ---------------------------------------------------------------------------
__global__ void k_zero_deg(int n) {
    int i = blockIdx.x * blockDim.x + threadIdx.x;
    if (i < n) g_dis[i] = 0.0f;
}

__global__ void k_deg(const int* __restrict__ ei,
                      const float* __restrict__ ew, int E) {
    int e = blockIdx.x * blockDim.x + threadIdx.x;
    if (e < E) {
        int c = ei[E + e];
        atomicAdd(&g_dis[c], ew[e]);
    }
}

__global__ void k_dis(int n) {
    int i = blockIdx.x * blockDim.x + threadIdx.x;
    if (i < n) g_dis[i] = rsqrtf(g_dis[i] + 1.0f);   // +1 = self-loop weight
}

// ---------------------------------------------------------------------------
// GEMM1: g_h1[N,64] = x[N,256] @ W1[256,64]
// Register-tiled: block = 256 thr, tile 128 rows x 64 cols, each thread 8x4.
// smem k-major: xs[k][row], ws[k][col]. 3x LDS.128 per k-step for 32 FMA.
// ---------------------------------------------------------------------------
#define G1_ROWS 128
#define G1_KCH  32

__global__ void k_gemm1(const float* __restrict__ x,
                        const float* __restrict__ W1) {
    __shared__ float xs[G1_KCH][G1_ROWS];   // 16 KB
    __shared__ float ws[G1_KCH][F_HID];     // 8 KB

    int t    = threadIdx.x;
    int row0 = blockIdx.x * G1_ROWS;
    int tx   = t & 15;        // col group: cols tx*4 .. +3
    int ty   = t >> 4;        // row group: rows ty*8 .. +7

    float acc[8][4];
    #pragma unroll
    for (int i = 0; i < 8; i++)
        #pragma unroll
        for (int j = 0; j < 4; j++) acc[i][j] = 0.0f;

    for (int kc = 0; kc < F_IN / G1_KCH; kc++) {
        // W chunk: 32x64 floats = 512 float4, contiguous (W1 is k-major already)
        const float4* w4 = (const float4*)(W1 + kc * G1_KCH * F_HID);
        ((float4*)ws)[t]       = w4[t];
        ((float4*)ws)[t + 256] = w4[t + 256];
        // x tile: 128 rows x 32 k = 1024 float4, transposed into xs[k][row]
        #pragma unroll
        for (int j = 0; j < 4; j++) {
            int idx = t + j * 256;
            int r   = idx & 127;
            int kq  = idx >> 7;                  // 0..7
            int gr  = row0 + r;
            if (gr >= N_NODES) gr = N_NODES - 1; // clamp (result discarded)
            float4 v = *(const float4*)(x + (size_t)gr * F_IN + kc * G1_KCH + kq * 4);
            xs[kq * 4 + 0][r] = v.x;
            xs[kq * 4 + 1][r] = v.y;
            xs[kq * 4 + 2][r] = v.z;
            xs[kq * 4 + 3][r] = v.w;
        }
        __syncthreads();

        #pragma unroll
        for (int kk = 0; kk < G1_KCH; kk++) {
            float4 a0 = *(const float4*)&xs[kk][ty * 8];
            float4 a1 = *(const float4*)&xs[kk][ty * 8 + 4];
            float4 b  = *(const float4*)&ws[kk][tx * 4];
            float av[8] = {a0.x, a0.y, a0.z, a0.w, a1.x, a1.y, a1.z, a1.w};
            #pragma unroll
            for (int i = 0; i < 8; i++) {
                acc[i][0] += av[i] * b.x;
                acc[i][1] += av[i] * b.y;
                acc[i][2] += av[i] * b.z;
                acc[i][3] += av[i] * b.w;
            }
        }
        __syncthreads();
    }

    #pragma unroll
    for (int i = 0; i < 8; i++) {
        int gr = row0 + ty * 8 + i;
        if (gr < N_NODES)
            *(float4*)(g_h1 + (size_t)gr * F_HID + tx * 4) =
                make_float4(acc[i][0], acc[i][1], acc[i][2], acc[i][3]);
    }
}

// ---------------------------------------------------------------------------
// Layer-1 edge aggregation: 16 threads per edge, float4 vectorized atomics
// ---------------------------------------------------------------------------
__global__ void k_zero_agg1(int n4) {
    int i = blockIdx.x * blockDim.x + threadIdx.x;
    if (i < n4) ((float4*)g_agg1)[i] = make_float4(0.f, 0.f, 0.f, 0.f);
}

__global__ void k_agg1(const int* __restrict__ ei,
                       const float* __restrict__ ew, int E) {
    int idx = blockIdx.x * blockDim.x + threadIdx.x;
    int e = idx >> 4;
    int c = idx & 15;
    if (e >= E) return;
    int r   = ei[e];
    int col = ei[E + e];
    float nrm = g_dis[r] * ew[e] * g_dis[col];
    float4 v = *(const float4*)(g_h1 + (size_t)r * F_HID + c * 4);
    atomicAdd((float4*)(g_agg1 + (size_t)col * F_HID + c * 4),
              make_float4(nrm * v.x, nrm * v.y, nrm * v.z, nrm * v.w));
}

// self loop + bias + relu, in place into g_agg1 (float4)
__global__ void k_selfrelu(const float* __restrict__ b1, int n4) {
    int idx4 = blockIdx.x * blockDim.x + threadIdx.x;
    if (idx4 >= n4) return;
    int i  = idx4 >> 4;          // node (16 float4 per row)
    int f4 = idx4 & 15;
    float d = g_dis[i];
    float s = d * d;
    float4 a = ((const float4*)g_agg1)[idx4];
    float4 h = ((const float4*)g_h1)[idx4];
    float4 b = ((const float4*)b1)[f4];
    float4 o;
    o.x = fmaxf(a.x + s * h.x + b.x, 0.0f);
    o.y = fmaxf(a.y + s * h.y + b.y, 0.0f);
    o.z = fmaxf(a.z + s * h.z + b.z, 0.0f);
    o.w = fmaxf(a.w + s * h.w + b.w, 0.0f);
    ((float4*)g_agg1)[idx4] = o;
}

// ---------------------------------------------------------------------------
// GEMM2: g_h2[N,40] = relu_out[N,64] @ W2[64,40]
// Register-tiled: 256 thr, tile 128 rows x 40 cols, each thread 4x5, full K=64.
// ---------------------------------------------------------------------------
__global__ void k_gemm2(const float* __restrict__ W2) {
    __shared__ float rs[F_HID][G1_ROWS];   // 64 x 128 = 32 KB, k-major
    __shared__ float ws2[F_HID][F_OUT];    // 10 KB

    int t    = threadIdx.x;
    int row0 = blockIdx.x * G1_ROWS;
    int tx   = t & 7;         // col group: cols tx*5 .. +4
    int ty   = t >> 3;        // row group: rows ty*4 .. +3

    // load W2 (2560 floats = 640 float4)
    #pragma unroll
    for (int j = 0; j < 3; j++) {
        int i = t + j * 256;
        if (i < 640) ((float4*)ws2)[i] = ((const float4*)W2)[i];
    }
    // load relu tile: 128 rows x 64 k = 2048 float4, transposed
    #pragma unroll
    for (int j = 0; j < 8; j++) {
        int idx = t + j * 256;
        int r   = idx & 127;
        int kq  = idx >> 7;                   // 0..15
        int gr  = row0 + r;
        if (gr >= N_NODES) gr = N_NODES - 1;
        float4 v = *(const float4*)(g_agg1 + (size_t)gr * F_HID + kq * 4);
        rs[kq * 4 + 0][r] = v.x;
        rs[kq * 4 + 1][r] = v.y;
        rs[kq * 4 + 2][r] = v.z;
        rs[kq * 4 + 3][r] = v.w;
    }
    __syncthreads();

    float acc[4][5];
    #pragma unroll
    for (int i = 0; i < 4; i++)
        #pragma unroll
        for (int j = 0; j < 5; j++) acc[i][j] = 0.0f;

    #pragma unroll
    for (int kk = 0; kk < F_HID; kk++) {
        float4 a = *(const float4*)&rs[kk][ty * 4];
        float av[4] = {a.x, a.y, a.z, a.w};
        #pragma unroll
        for (int j = 0; j < 5; j++) {
            float b = ws2[kk][tx * 5 + j];
            #pragma unroll
            for (int i = 0; i < 4; i++)
                acc[i][j] += av[i] * b;
        }
    }

    #pragma unroll
    for (int i = 0; i < 4; i++) {
        int gr = row0 + ty * 4 + i;
        if (gr < N_NODES) {
            float* o = g_h2 + (size_t)gr * F_OUT + tx * 5;
            #pragma unroll
            for (int j = 0; j < 5; j++) o[j] = acc[i][j];
        }
    }
}

// init output with bias + self-loop contribution (float4, 10 per row)
__global__ void k_init_out(const float* __restrict__ b2,
                           float* __restrict__ out, int n4) {
    int idx4 = blockIdx.x * blockDim.x + threadIdx.x;
    if (idx4 >= n4) return;
    int i  = idx4 / 10;
    int f4 = idx4 - i * 10;
    float d = g_dis[i];
    float s = d * d;
    float4 h = ((const float4*)g_h2)[idx4];
    float4 b = ((const float4*)b2)[f4];
    ((float4*)out)[idx4] =
        make_float4(b.x + s * h.x, b.y + s * h.y, b.z + s * h.z, b.w + s * h.w);
}

// Layer-2 edge aggregation: 10 float4 per edge
__global__ void k_agg2(const int* __restrict__ ei,
                       const float* __restrict__ ew,
                       float* __restrict__ out, int E) {
    int idx = blockIdx.x * blockDim.x + threadIdx.x;
    int e = idx / 10;
    int c = idx - e * 10;
    if (e >= E) return;
    int r   = ei[e];
    int col = ei[E + e];
    float nrm = g_dis[r] * ew[e] * g_dis[col];
    float4 v = *(const float4*)(g_h2 + (size_t)r * F_OUT + c * 4);
    atomicAdd((float4*)(out + (size_t)col * F_OUT + c * 4),
              make_float4(nrm * v.x, nrm * v.y, nrm * v.z, nrm * v.w));
}

// ---------------------------------------------------------------------------
extern "C" void kernel_launch(void* const* d_in, const int* in_sizes, int n_in,
                              void* d_out, int out_size) {
    const float* x  = (const float*)d_in[0];
    const int*   ei = (const int*)d_in[1];
    const float* ew = (const float*)d_in[2];
    const float* W1 = (const float*)d_in[3];
    const float* b1 = (const float*)d_in[4];
    const float* W2 = (const float*)d_in[5];
    const float* b2 = (const float*)d_in[6];
    float* out = (float*)d_out;

    int N = in_sizes[0] / F_IN;     // 100000
    int E = in_sizes[2];            // 1600000

    k_zero_deg<<<(N + 255) / 256, 256>>>(N);
    k_deg<<<(E + 255) / 256, 256>>>(ei, ew, E);
    k_dis<<<(N + 255) / 256, 256>>>(N);

    int gemm_grid = (N + G1_ROWS - 1) / G1_ROWS;   // 782
    k_gemm1<<<gemm_grid, 256>>>(x, W1);

    int n1_4 = N * F_HID / 4;
    k_zero_agg1<<<(n1_4 + 255) / 256, 256>>>(n1_4);
    {
        long long items = (long long)E * 16;
        k_agg1<<<(int)((items + 255) / 256), 256>>>(ei, ew, E);
    }
    k_selfrelu<<<(n1_4 + 255) / 256, 256>>>(b1, n1_4);

    k_gemm2<<<gemm_grid, 256>>>(W2);

    int n2_4 = N * F_OUT / 4;
    k_init_out<<<(n2_4 + 255) / 256, 256>>>(b2, out, n2_4);
    {
        long long items = (long long)E * 10;
        k_agg2<<<(int)((items + 255) / 256), 256>>>(ei, ew, out, E);
    }
}